// round 16
// baseline (speedup 1.0000x reference)
#include <cuda_runtime.h>
#include <cuda_bf16.h>
#include <math.h>
#include <cstdint>
#include <cstddef>

#define BB 8
#define SS 1024
#define HH 768
#define TT 8
#define DDI 64
#define HIDD 128
#define KSP 8
#define NHEADS 2
#define NN 9
#define FF 256      // NHEADS*HIDD
#define OUTD 1024   // TT*2*DDI
#define KEP 96      // 64 rope + 16 gaussian + 16 zero pad
#define KSPLIT 4
#define KCH (HH / KSPLIT)   // 192
#define NEGC 1000000000000.0f
#define L2C 0.41524101186092573f   // log2(10000)/32

// prep dispatch ranges
#define PREP_CVTHID 6144                 // (BB*SS*HH)/1024
#define PREP_CVTW   (PREP_CVTHID + 768)  // (OUTD/32)*(HH/32)
#define PREP_TOTAL  (PREP_CVTW + 128)    // + 16*BB part blocks

// triangular tile decode (m<=n upper incl diagonal: 36; m>n lower: 28)
__constant__ int TRI_M[36] = {0,0,0,0,0,0,0,0, 1,1,1,1,1,1,1, 2,2,2,2,2,2,
                              3,3,3,3,3, 4,4,4,4, 5,5,5, 6,6, 7};
__constant__ int TRI_N[36] = {0,1,2,3,4,5,6,7, 1,2,3,4,5,6,7, 2,3,4,5,6,7,
                              3,4,5,6,7, 4,5,6,7, 5,6,7, 6,7, 7};
__constant__ int LO_M[28] = {1, 2,2, 3,3,3, 4,4,4,4, 5,5,5,5,5,
                             6,6,6,6,6,6, 7,7,7,7,7,7,7};
__constant__ int LO_N[28] = {0, 0,1, 0,1,2, 0,1,2,3, 0,1,2,3,4,
                             0,1,2,3,4,5, 0,1,2,3,4,5,6};

// ------------------- device scratch -------------------
__device__ float d_gfpart[BB * 8 * HH];
__device__ float d_nodes[BB * NN * HH];
__device__ float d_h1p[KSPLIT * BB * NN * FF];
__device__ float d_eW[BB * OUTD];
__device__ float d_cover[BB * SS];
__device__ __nv_bfloat16 d_hidbf[(size_t)BB * SS * HH];
__device__ __nv_bfloat16 d_wbf[(size_t)OUTD * HH];               // W^T bf16 [n][k]
__device__ __nv_bfloat16 d_qext[(size_t)BB * TT * SS * KEP];
__device__ __nv_bfloat16 d_kext[(size_t)BB * TT * SS * KEP];

__device__ __forceinline__ uint32_t smem_u32(const void* p) {
    uint32_t a;
    asm("{ .reg .u64 t; cvta.to.shared.u64 t, %1; cvt.u32.u64 %0, t; }" : "=r"(a) : "l"(p));
    return a;
}

#define CP16(dst, src) \
    asm volatile("cp.async.cg.shared.global [%0], [%1], 16;" :: "r"(dst), "l"(src))
#define CP_COMMIT() asm volatile("cp.async.commit_group;")
#define CP_WAIT(n)  asm volatile("cp.async.wait_group %0;" :: "n"(n))

__device__ __forceinline__ void stcs2(float* p, float x, float y) {
    asm volatile("st.global.cs.v2.f32 [%0], {%1, %2};" :: "l"(p), "f"(x), "f"(y) : "memory");
}
__device__ __forceinline__ void stcs4(float* p, float4 v) {
    asm volatile("st.global.cs.v4.f32 [%0], {%1, %2, %3, %4};"
                 :: "l"(p), "f"(v.x), "f"(v.y), "f"(v.z), "f"(v.w) : "memory");
}

// ------------------- aux stream (static init; proven pattern from R9/R11) -------------------
namespace {
struct AuxRes {
    cudaStream_t s = nullptr;
    cudaEvent_t e_fork = nullptr, e_join = nullptr;
    bool ok = false;
    AuxRes() {
        ok = cudaStreamCreateWithFlags(&s, cudaStreamNonBlocking) == cudaSuccess &&
             cudaEventCreateWithFlags(&e_fork, cudaEventDisableTiming) == cudaSuccess &&
             cudaEventCreateWithFlags(&e_join, cudaEventDisableTiming) == cudaSuccess;
    }
};
AuxRes g_aux;
}

// --------- lower-triangle constant fill: depends ONLY on mask; overlapped with main chain ---------
__global__ void k_fill(const float* __restrict__ mask, float* __restrict__ out) {
    int id = blockIdx.x;
    int bt = blockIdx.y;
    int b = bt >> 3;
    int tid = threadIdx.x;
    int m0 = LO_M[id] * 128, n0 = LO_N[id] * 128;
    int colq = (tid & 31) * 4;
    float4 pd = *(const float4*)&mask[b * SS + n0 + colq];
    float4 v;
    v.x = (-(1.f - pd.x) * NEGC - NEGC) * 0.125f;
    v.y = (-(1.f - pd.y) * NEGC - NEGC) * 0.125f;
    v.z = (-(1.f - pd.z) * NEGC - NEGC) * 0.125f;
    v.w = (-(1.f - pd.w) * NEGC - NEGC) * 0.125f;
    int r0 = tid >> 5;
    #pragma unroll
    for (int p = 0; p < 16; p++) {
        int m = m0 + p * 8 + r0;
        stcs4(&out[((size_t)bt * SS + m) * SS + n0 + colq], v);
    }
}

// ------- fused prep: hidden->bf16, W-top transpose->bf16, gfpart/span-nodes/cover -------
__global__ void k_prep(const float* __restrict__ hidden, const int* __restrict__ spans,
                       const float* __restrict__ W) {
    int bid = blockIdx.x;
    int tid = threadIdx.x;
    if (bid < PREP_CVTHID) {
        int i = (bid * 256 + tid) * 4;
        float4 v = *(const float4*)&hidden[i];
        __nv_bfloat162* o = (__nv_bfloat162*)&d_hidbf[i];
        o[0] = __floats2bfloat162_rn(v.x, v.y);
        o[1] = __floats2bfloat162_rn(v.z, v.w);
    } else if (bid < PREP_CVTW) {
        __shared__ float t[32][33];
        int tile = bid - PREP_CVTHID;
        int n0 = (tile & 31) * 32, k0 = (tile >> 5) * 32;
        int tx = tid & 31, ty = tid >> 5;
        #pragma unroll
        for (int i = 0; i < 32; i += 8)
            t[ty + i][tx] = W[(size_t)(k0 + ty + i) * OUTD + n0 + tx];
        __syncthreads();
        #pragma unroll
        for (int i = 0; i < 32; i += 8)
            d_wbf[(size_t)(n0 + ty + i) * HH + k0 + tx] = __float2bfloat16(t[tx][ty + i]);
    } else {
        int idx = bid - PREP_CVTW;
        int p = idx & 15, b = idx >> 4;
        if (p < 8) {
            if (tid < 128) {
                int s = p * 128 + tid;
                const int* sp = spans + b * KSP * 3;
                float c = 0.f;
                #pragma unroll
                for (int k = 0; k < KSP; k++) {
                    int st = sp[k * 3], en = sp[k * 3 + 1];
                    c += (s >= st && s <= en) ? 1.f : 0.f;
                }
                d_cover[b * SS + s] = c;
            }
            for (int c = tid; c < HH; c += 256) {
                float acc = 0.f;
                const float* base = hidden + ((size_t)b * SS + (size_t)p * 128) * HH + c;
                #pragma unroll 4
                for (int s = 0; s < 128; s++) acc += base[(size_t)s * HH];
                d_gfpart[(b * 8 + p) * HH + c] = acc;
            }
        } else {
            int k = p - 8;
            int st = spans[(b * KSP + k) * 3 + 0];
            int en = spans[(b * KSP + k) * 3 + 1];
            float inv = 1.f / (float)(en - st + 1);
            for (int c = tid; c < HH; c += 256) {
                float a = 0.f;
                for (int s = st; s <= en; s++) a += hidden[((size_t)b * SS + s) * HH + c];
                d_nodes[(b * NN + 1 + k) * HH + c] = a * inv;
            }
        }
    }
}

// ---------- h1 partial GEMM: k-split 4-way ----------
__global__ void k_h1(const float* __restrict__ W1) {
    int n = blockIdx.x, b = blockIdx.y, z = blockIdx.z;
    int tid = threadIdx.x;
    __shared__ float sX[KCH];
    int k0 = z * KCH;
    if (n == 0) {
        for (int c = tid; c < KCH; c += 256) {
            float g = 0.f;
            #pragma unroll
            for (int p = 0; p < 8; p++) g += d_gfpart[(b * 8 + p) * HH + k0 + c];
            sX[c] = g * (1.f / (float)SS);
        }
    } else {
        for (int c = tid; c < KCH; c += 256) sX[c] = d_nodes[(b * NN + n) * HH + k0 + c];
    }
    __syncthreads();
    float acc = 0.f;
    #pragma unroll 8
    for (int d = 0; d < KCH; d++) acc += sX[d] * W1[(size_t)(k0 + d) * FF + tid];
    d_h1p[((z * BB + b) * NN + n) * FF + tid] = acc;
}

// --------- softmax over graph neighbors ---------
__device__ __forceinline__ void attn_softmax(const float* sAdjLog, const float* sAS,
                                             const float* sAD, float* sAttn, int tid) {
    if (tid < NN * NHEADS) {
        int i = tid / NHEADS, head = tid % NHEADS;
        float sc[NN];
        float mx = -1e30f;
        #pragma unroll
        for (int j = 0; j < NN; j++) {
            float al = sAdjLog[i * NN + j];
            float v;
            if (al > -1e29f) {
                float e = sAD[i * NHEADS + head] + sAS[j * NHEADS + head];
                e = (e >= 0.f) ? e : 0.2f * e;
                v = e + al;
            } else v = -1e30f;
            sc[j] = v;
            mx = fmaxf(mx, v);
        }
        float ssum = 0.f;
        #pragma unroll
        for (int j = 0; j < NN; j++) { float e = expf(sc[j] - mx); sc[j] = e; ssum += e; }
        float inv = 1.f / ssum;
        #pragma unroll
        for (int j = 0; j < NN; j++) sAttn[(i * NN + j) * NHEADS + head] = sc[j] * inv;
    }
}

// ------ fused graph tail ------
__global__ void k_graphtail(const int* __restrict__ spans,
                            const float* __restrict__ asrc1, const float* __restrict__ adst1,
                            const float* __restrict__ b1,
                            const float* __restrict__ lng, const float* __restrict__ lnb,
                            const float* __restrict__ W2, const float* __restrict__ asrc2,
                            const float* __restrict__ adst2, const float* __restrict__ b2,
                            const float* __restrict__ dW) {
    int b = blockIdx.x, tid = threadIdx.x;
    __shared__ float sH[NN * FF];
    __shared__ float sG[NN * FF];
    __shared__ float sAdjLog[NN * NN];
    __shared__ float sAS[NN * NHEADS], sAD[NN * NHEADS];
    __shared__ float sAttn[NN * NN * NHEADS];
    __shared__ int sSp[KSP * 2];
    __shared__ float sWred[16], sRed[2];
    __shared__ float sE[FF];

    for (int i = tid; i < NN * FF; i += 256) {
        float v = 0.f;
        #pragma unroll
        for (int z = 0; z < KSPLIT; z++) v += d_h1p[(z * BB + b) * NN * FF + i];
        sH[i] = v;
    }
    if (tid < KSP * 2) sSp[tid] = spans[(b * KSP + tid / 2) * 3 + (tid & 1)];
    __syncthreads();

    if (tid < NN * NHEADS * 2) {
        int n = tid / (NHEADS * 2);
        int rem = tid % (NHEADS * 2);
        int head = rem % NHEADS;
        int isd = rem / NHEADS;
        const float* av = isd ? adst1 : asrc1;
        float acc = 0.f;
        for (int f = 0; f < HIDD; f++) acc += sH[n * FF + head * HIDD + f] * av[head * HIDD + f];
        if (isd) sAD[n * NHEADS + head] = acc;
        else     sAS[n * NHEADS + head] = acc;
    }
    if (tid >= 64 && tid - 64 < NN * NN) {
        int t2 = tid - 64;
        int r = t2 / NN, c = t2 % NN;
        float v = 0.f;
        if (r == c) v += 1.f;
        if (c == 0 && r >= 1) v += 1.f;
        if (r == 0 && c >= 1) v += 1.f;
        if (r >= 1 && c >= 1 && r != c) {
            int i = r - 1, j = c - 1;
            int si = sSp[i * 2], ei = sSp[i * 2 + 1];
            int sj = sSp[j * 2], ej = sSp[j * 2 + 1];
            bool same = (sj == si) && (ej == ei);
            if ((sj <= si) && (ei <= ej) && !same) v += 2.f;
        }
        sAdjLog[t2] = (v > 0.f) ? logf(v) : -1e30f;
    }
    __syncthreads();
    attn_softmax(sAdjLog, sAS, sAD, sAttn, tid);
    __syncthreads();

    {
        int head = tid / HIDD;
        float bb = b1[tid];
        #pragma unroll
        for (int i = 0; i < NN; i++) {
            float acc = bb;
            #pragma unroll
            for (int j = 0; j < NN; j++) acc += sAttn[(i * NN + j) * NHEADS + head] * sH[j * FF + tid];
            sG[i * FF + tid] = fmaxf(acc, 0.f);
        }
    }
    __syncthreads();
    float gw = lng[tid], gb = lnb[tid];
    for (int i = 0; i < NN; i++) {
        float v = sG[i * FF + tid];
        float s1 = v, s2 = v * v;
        #pragma unroll
        for (int o = 16; o > 0; o >>= 1) {
            s1 += __shfl_down_sync(0xffffffffu, s1, o);
            s2 += __shfl_down_sync(0xffffffffu, s2, o);
        }
        int wid = tid >> 5, lane = tid & 31;
        if (lane == 0) { sWred[wid] = s1; sWred[8 + wid] = s2; }
        __syncthreads();
        if (tid == 0) {
            float a = 0.f, q = 0.f;
            #pragma unroll
            for (int w = 0; w < 8; w++) { a += sWred[w]; q += sWred[8 + w]; }
            float mu = a / (float)FF;
            float var = q / (float)FF - mu * mu;
            sRed[0] = mu;
            sRed[1] = rsqrtf(var + 1e-5f);
        }
        __syncthreads();
        sG[i * FF + tid] = (v - sRed[0]) * sRed[1] * gw + gb;
        __syncthreads();
    }

    {
        float acc2[NN];
        #pragma unroll
        for (int n = 0; n < NN; n++) acc2[n] = 0.f;
        #pragma unroll 8
        for (int d = 0; d < FF; d++) {
            float w = W2[(size_t)d * FF + tid];
            #pragma unroll
            for (int n = 0; n < NN; n++) acc2[n] += sG[n * FF + d] * w;
        }
        #pragma unroll
        for (int n = 0; n < NN; n++) sH[n * FF + tid] = acc2[n];
    }
    __syncthreads();
    if (tid < NN * NHEADS * 2) {
        int n = tid / (NHEADS * 2);
        int rem = tid % (NHEADS * 2);
        int head = rem % NHEADS;
        int isd = rem / NHEADS;
        const float* av = isd ? adst2 : asrc2;
        float acc = 0.f;
        for (int f = 0; f < HIDD; f++) acc += sH[n * FF + head * HIDD + f] * av[head * HIDD + f];
        if (isd) sAD[n * NHEADS + head] = acc;
        else     sAS[n * NHEADS + head] = acc;
    }
    __syncthreads();
    attn_softmax(sAdjLog, sAS, sAD, sAttn, tid);
    __syncthreads();

    {
        int head = tid / HIDD;
        float bb = b2[tid];
        float esum = 0.f;
        #pragma unroll
        for (int i = 0; i < NN; i++) {
            float acc = bb;
            #pragma unroll
            for (int j = 0; j < NN; j++) acc += sAttn[(i * NN + j) * NHEADS + head] * sH[j * FF + tid];
            esum += fmaxf(acc, 0.f);
        }
        sE[tid] = esum * (1.f / (float)NN);
    }
    __syncthreads();

    {
        float acc[4] = {};
        #pragma unroll 4
        for (int c = 0; c < FF; c++) {
            float e = sE[c];
            const float* row = dW + (size_t)(HH + c) * OUTD + tid;
            #pragma unroll
            for (int j = 0; j < 4; j++) acc[j] += e * row[j * 256];
        }
        #pragma unroll
        for (int j = 0; j < 4; j++) d_eW[b * OUTD + tid + j * 256] = acc[j];
    }
}

// ------------------- bf16 MMA building blocks -------------------
__device__ __forceinline__ void g2s_cp(uint32_t dA, uint32_t dB,
        const __nv_bfloat16* __restrict__ A, const __nv_bfloat16* __restrict__ B,
        int strA, int strB, int m0, int n0, int kk, int tid) {
    #pragma unroll
    for (int i = 0; i < 2; i++) {
        int lin = tid + i * 256;
        int row = lin >> 2, ch = lin & 3;
        uint32_t off = (uint32_t)(row * 4 + (ch ^ ((row >> 1) & 3))) * 16;
        CP16(dA + off, A + (size_t)(m0 + row) * strA + kk + ch * 8);
        CP16(dB + off, B + (size_t)(n0 + row) * strB + kk + ch * 8);
    }
    CP_COMMIT();
}

__device__ __forceinline__ void tile_compute(uint32_t baseA, uint32_t baseB,
                                             int wm0, int wn0, int lane,
                                             float (&acc)[4][4][4]) {
    int rowAo = lane & 15, chAo = lane >> 4;
    int rowBo = (lane & 7) + ((lane & 16) >> 1), chBo = (lane >> 3) & 1;
    #pragma unroll
    for (int ks = 0; ks < 2; ks++) {
        uint32_t a[4][4], b[2][4];
        #pragma unroll
        for (int mi = 0; mi < 4; mi++) {
            int row = wm0 + mi * 16 + rowAo;
            int ch = ks * 2 + chAo;
            uint32_t addr = baseA + row * 64 + ((ch ^ ((row >> 1) & 3)) << 4);
            asm volatile("ldmatrix.sync.aligned.m8n8.x4.shared.b16 {%0,%1,%2,%3}, [%4];"
                : "=r"(a[mi][0]), "=r"(a[mi][1]), "=r"(a[mi][2]), "=r"(a[mi][3]) : "r"(addr));
        }
        #pragma unroll
        for (int ng = 0; ng < 2; ng++) {
            int row = wn0 + ng * 16 + rowBo;
            int ch = ks * 2 + chBo;
            uint32_t addr = baseB + row * 64 + ((ch ^ ((row >> 1) & 3)) << 4);
            asm volatile("ldmatrix.sync.aligned.m8n8.x4.shared.b16 {%0,%1,%2,%3}, [%4];"
                : "=r"(b[ng][0]), "=r"(b[ng][1]), "=r"(b[ng][2]), "=r"(b[ng][3]) : "r"(addr));
        }
        #pragma unroll
        for (int mi = 0; mi < 4; mi++)
            #pragma unroll
            for (int ni = 0; ni < 4; ni++) {
                uint32_t b0 = b[ni >> 1][(ni & 1) * 2 + 0];
                uint32_t b1 = b[ni >> 1][(ni & 1) * 2 + 1];
                asm volatile("mma.sync.aligned.m16n8k16.row.col.f32.bf16.bf16.f32 "
                    "{%0,%1,%2,%3}, {%4,%5,%6,%7}, {%8,%9}, {%0,%1,%2,%3};"
                    : "+f"(acc[mi][ni][0]), "+f"(acc[mi][ni][1]),
                      "+f"(acc[mi][ni][2]), "+f"(acc[mi][ni][3])
                    : "r"(a[mi][0]), "r"(a[mi][1]), "r"(a[mi][2]), "r"(a[mi][3]),
                      "r"(b0), "r"(b1));
            }
    }
}

// ----- GEMM1 fused: qk = hid@W^T + cover*eW + db, RoPE (fast sincos), + gaussian extras -----
__global__ void __launch_bounds__(256, 2) k_gemm1_mma(const float* __restrict__ db,
        const int* __restrict__ spans, const float* __restrict__ gc,
        const float* __restrict__ gs, const float* __restrict__ gw,
        const float* __restrict__ corr) {
    __shared__ uint4 sA[3][512], sB[3][512];
    int tid = threadIdx.x, lane = tid & 31, wid = tid >> 5;
    int m0 = blockIdx.y * 128, n0 = blockIdx.x * 128;
    int wm0 = (wid & 1) * 64, wn0 = (wid >> 1) * 32;
    float acc[4][4][4] = {};
    const int NT = HH / 32;   // 24
    g2s_cp(smem_u32(sA[0]), smem_u32(sB[0]), d_hidbf, d_wbf, HH, HH, m0, n0, 0, tid);
    g2s_cp(smem_u32(sA[1]), smem_u32(sB[1]), d_hidbf, d_wbf, HH, HH, m0, n0, 32, tid);
    for (int it = 0; it < NT; ++it) {
        CP_WAIT(1);
        __syncthreads();
        int cur = it % 3;
        tile_compute(smem_u32(sA[cur]), smem_u32(sB[cur]), wm0, wn0, lane, acc);
        if (it + 2 < NT) {
            int nxt = (it + 2) % 3;
            g2s_cp(smem_u32(sA[nxt]), smem_u32(sB[nxt]), d_hidbf, d_wbf, HH, HH,
                   m0, n0, (it + 2) * 32, tid);
        } else {
            CP_COMMIT();
        }
    }
    int g = lane >> 2, tq = lane & 3;
    int t = blockIdx.x;
    #pragma unroll
    for (int mi = 0; mi < 4; mi++) {
        #pragma unroll
        for (int half = 0; half < 2; half++) {
            int r = m0 + wm0 + mi * 16 + g + half * 8;
            int b = r >> 10, s = r & (SS - 1);
            float cov = d_cover[r];
            float sf = (float)s;
            size_t rowbase = ((size_t)(b * TT + t) * SS + s) * KEP;
            #pragma unroll
            for (int ni = 0; ni < 4; ni++) {
                int jj = wn0 + ni * 8 + tq * 2;
                int c = n0 + jj;
                float2 ew = *(const float2*)&d_eW[b * OUTD + c];
                float2 dbv = *(const float2*)&db[c];
                float x = acc[mi][ni][half * 2 + 0] + cov * ew.x + dbv.x;
                float y = acc[mi][ni][half * 2 + 1] + cov * ew.y + dbv.y;
                int i = (jj & 63) >> 1;
                float ang = sf * exp2f(-(float)i * L2C);
                float sv, cvv;
                __sincosf(ang, &sv, &cvv);
                __nv_bfloat162 v = __floats2bfloat162_rn(x * cvv - y * sv, y * cvv + x * sv);
                __nv_bfloat16* dst = ((jj < 64) ? d_qext : d_kext) + rowbase + (jj & 63);
                *(__nv_bfloat162*)dst = v;
            }
        }
    }
    // gaussian extras
    {
        int r = m0 + (tid & 127);
        int b = r >> 10, s = r & (SS - 1);
        bool isq = tid < 128;
        float sf = (float)s;
        const int* sp = spans + b * KSP * 3;
        float g0w = gw[0], g1w = gw[1];
        float g0c = gc[0], g1c = gc[1];
        float g0si = 1.f / gs[0], g1si = 1.f / gs[1];
        __nv_bfloat162* dst = (__nv_bfloat162*)(
            (isq ? d_qext : d_kext) + ((size_t)(b * TT + t) * SS + s) * KEP + 64);
        #pragma unroll
        for (int kk = 0; kk < KSP; kk++) {
            int st = sp[kk * 3], en = sp[kk * 3 + 1], et = sp[kk * 3 + 2];
            float base = isq ? (float)st : (float)en;
            float mult = isq ? corr[et * TT + t] : 1.f;
            float d0 = (sf - base - g0c) * g0si;
            float d1 = (sf - base - g1c) * g1si;
            dst[kk] = __floats2bfloat162_rn(mult * g0w * __expf(-0.5f * d0 * d0),
                                            mult * g1w * __expf(-0.5f * d1 * d1));
        }
        __nv_bfloat162 z = __floats2bfloat162_rn(0.f, 0.f);
        #pragma unroll
        for (int i = 8; i < 16; i++) dst[i] = z;
    }
}

// ------------- GEMM2: upper-triangle tiles only (prefetch-all, streaming stores) -------------
__global__ void __launch_bounds__(256, 2) k_gemm2_mma(const float* __restrict__ mask,
                                                      float* __restrict__ out) {
    __shared__ uint4 sA[3][512], sB[3][512];
    int id = blockIdx.x;
    int bt = blockIdx.y;
    int b = bt >> 3;
    int tid = threadIdx.x;
    int m0 = TRI_M[id] * 128, n0 = TRI_N[id] * 128;

    const __nv_bfloat16* Ab = d_qext + (size_t)bt * SS * KEP;
    const __nv_bfloat16* Bb = d_kext + (size_t)bt * SS * KEP;
    int lane = tid & 31, wid = tid >> 5;
    int wm0 = (wid & 1) * 64, wn0 = (wid >> 1) * 32;
    float acc[4][4][4] = {};
    #pragma unroll
    for (int st = 0; st < 3; st++)
        g2s_cp(smem_u32(sA[st]), smem_u32(sB[st]), Ab, Bb, KEP, KEP, m0, n0, st * 32, tid);
    CP_WAIT(0);
    __syncthreads();
    #pragma unroll
    for (int st = 0; st < 3; st++)
        tile_compute(smem_u32(sA[st]), smem_u32(sB[st]), wm0, wn0, lane, acc);

    int g = lane >> 2, tq = lane & 3;
    #pragma unroll
    for (int mi = 0; mi < 4; mi++) {
        #pragma unroll
        for (int half = 0; half < 2; half++) {
            int m = m0 + wm0 + mi * 16 + g + half * 8;
            #pragma unroll
            for (int ni = 0; ni < 4; ni++) {
                int n = n0 + wn0 + ni * 8 + tq * 2;
                float2 pd = *(const float2*)&mask[b * SS + n];
                float v0 = acc[mi][ni][half * 2 + 0] * pd.x - (1.f - pd.x) * NEGC;
                float v1 = acc[mi][ni][half * 2 + 1] * pd.y - (1.f - pd.y) * NEGC;
                if (m > n)     v0 -= NEGC;
                if (m > n + 1) v1 -= NEGC;
                stcs2(&out[((size_t)bt * SS + m) * SS + n], v0 * 0.125f, v1 * 0.125f);
            }
        }
    }
}

// ------------------- launch -------------------
extern "C" void kernel_launch(void* const* d_in, const int* in_sizes, int n_in,
                              void* d_out, int out_size) {
    const float* hidden = (const float*)d_in[0];
    const float* amask  = (const float*)d_in[1];
    const int*   spans  = (const int*)d_in[2];
    const float* W1     = (const float*)d_in[3];
    const float* asrc1  = (const float*)d_in[4];
    const float* adst1  = (const float*)d_in[5];
    const float* b1     = (const float*)d_in[6];
    const float* lng    = (const float*)d_in[7];
    const float* lnb    = (const float*)d_in[8];
    const float* W2     = (const float*)d_in[9];
    const float* asrc2  = (const float*)d_in[10];
    const float* adst2  = (const float*)d_in[11];
    const float* b2     = (const float*)d_in[12];
    const float* dW     = (const float*)d_in[13];
    const float* db     = (const float*)d_in[14];
    const float* gc     = (const float*)d_in[15];
    const float* gsg    = (const float*)d_in[16];
    const float* gwt    = (const float*)d_in[17];
    const float* corr   = (const float*)d_in[18];
    float* out = (float*)d_out;

    bool fork = g_aux.ok;
    if (fork) {
        cudaEventRecord(g_aux.e_fork, 0);
        cudaStreamWaitEvent(g_aux.s, g_aux.e_fork, 0);
        // lower-triangle fill depends ONLY on mask — runs concurrent with entire chain
        k_fill<<<dim3(28, BB * TT), 256, 0, g_aux.s>>>(amask, out);
        cudaEventRecord(g_aux.e_join, g_aux.s);
    } else {
        k_fill<<<dim3(28, BB * TT), 256>>>(amask, out);
    }
    k_prep<<<PREP_TOTAL, 256>>>(hidden, spans, dW);
    k_h1<<<dim3(NN, BB, KSPLIT), 256>>>(W1);
    k_graphtail<<<BB, 256>>>(spans, asrc1, adst1, b1, lng, lnb,
                             W2, asrc2, adst2, b2, dW);
    k_gemm1_mma<<<dim3(OUTD / 128, (BB * SS) / 128), 256>>>(db, spans, gc, gsg, gwt, corr);
    k_gemm2_mma<<<dim3(36, BB * TT), 256>>>(amask, out);
    if (fork) cudaStreamWaitEvent(0, g_aux.e_join, 0);
}

// round 17
// speedup vs baseline: 1.2152x; 1.2152x over previous
#include <cuda_runtime.h>
#include <cuda_bf16.h>
#include <math.h>
#include <cstdint>
#include <cstddef>

#define BB 8
#define SS 1024
#define HH 768
#define TT 8
#define DDI 64
#define HIDD 128
#define KSP 8
#define NHEADS 2
#define NN 9
#define FF 256      // NHEADS*HIDD
#define OUTD 1024   // TT*2*DDI
#define KEP 96      // 64 rope + 16 gaussian + 16 zero pad
#define KSPLIT 4
#define KCH (HH / KSPLIT)   // 192
#define NEGC 1000000000000.0f
#define L2C 0.41524101186092573f   // log2(10000)/32

// prep dispatch ranges
#define PREP_CVTHID 6144                 // (BB*SS*HH)/1024
#define PREP_CVTW   (PREP_CVTHID + 768)  // (OUTD/32)*(HH/32)
#define PREP_TOTAL  (PREP_CVTW + 128)    // + 16*BB part blocks

// ------------------- device scratch -------------------
__device__ float d_gfpart[BB * 8 * HH];
__device__ float d_nodes[BB * NN * HH];
__device__ float d_h1p[KSPLIT * BB * NN * FF];
__device__ float d_g1[BB * NN * FF];
__device__ float d_h2[BB * NN * FF];
__device__ float d_as2[BB * NN * NHEADS], d_ad2[BB * NN * NHEADS];
__device__ float d_enh[BB * FF];
__device__ float d_eW[BB * OUTD];
__device__ float d_cover[BB * SS];
__device__ __nv_bfloat16 d_hidbf[(size_t)BB * SS * HH];
__device__ __nv_bfloat16 d_wbf[(size_t)OUTD * HH];               // W^T bf16 [n][k]
__device__ __nv_bfloat16 d_qext[(size_t)BB * TT * SS * KEP];
__device__ __nv_bfloat16 d_kext[(size_t)BB * TT * SS * KEP];

__device__ __forceinline__ uint32_t smem_u32(const void* p) {
    uint32_t a;
    asm("{ .reg .u64 t; cvta.to.shared.u64 t, %1; cvt.u32.u64 %0, t; }" : "=r"(a) : "l"(p));
    return a;
}

#define CP16(dst, src) \
    asm volatile("cp.async.cg.shared.global [%0], [%1], 16;" :: "r"(dst), "l"(src))
#define CP_COMMIT() asm volatile("cp.async.commit_group;")
#define CP_WAIT(n)  asm volatile("cp.async.wait_group %0;" :: "n"(n))

__device__ __forceinline__ void stcs2(float* p, float x, float y) {
    asm volatile("st.global.cs.v2.f32 [%0], {%1, %2};" :: "l"(p), "f"(x), "f"(y) : "memory");
}
__device__ __forceinline__ void stcs4(float* p, float4 v) {
    asm volatile("st.global.cs.v4.f32 [%0], {%1, %2, %3, %4};"
                 :: "l"(p), "f"(v.x), "f"(v.y), "f"(v.z), "f"(v.w) : "memory");
}

// ------- fused prep: hidden->bf16, W-top transpose->bf16, gfpart/span-nodes/cover -------
__global__ void k_prep(const float* __restrict__ hidden, const int* __restrict__ spans,
                       const float* __restrict__ W) {
    int bid = blockIdx.x;
    int tid = threadIdx.x;
    if (bid < PREP_CVTHID) {
        int i = (bid * 256 + tid) * 4;
        float4 v = *(const float4*)&hidden[i];
        __nv_bfloat162* o = (__nv_bfloat162*)&d_hidbf[i];
        o[0] = __floats2bfloat162_rn(v.x, v.y);
        o[1] = __floats2bfloat162_rn(v.z, v.w);
    } else if (bid < PREP_CVTW) {
        __shared__ float t[32][33];
        int tile = bid - PREP_CVTHID;
        int n0 = (tile & 31) * 32, k0 = (tile >> 5) * 32;
        int tx = tid & 31, ty = tid >> 5;
        #pragma unroll
        for (int i = 0; i < 32; i += 8)
            t[ty + i][tx] = W[(size_t)(k0 + ty + i) * OUTD + n0 + tx];
        __syncthreads();
        #pragma unroll
        for (int i = 0; i < 32; i += 8)
            d_wbf[(size_t)(n0 + ty + i) * HH + k0 + tx] = __float2bfloat16(t[tx][ty + i]);
    } else {
        int idx = bid - PREP_CVTW;
        int p = idx & 15, b = idx >> 4;
        if (p < 8) {
            if (tid < 128) {
                int s = p * 128 + tid;
                const int* sp = spans + b * KSP * 3;
                float c = 0.f;
                #pragma unroll
                for (int k = 0; k < KSP; k++) {
                    int st = sp[k * 3], en = sp[k * 3 + 1];
                    c += (s >= st && s <= en) ? 1.f : 0.f;
                }
                d_cover[b * SS + s] = c;
            }
            for (int c = tid; c < HH; c += 256) {
                float acc = 0.f;
                const float* base = hidden + ((size_t)b * SS + (size_t)p * 128) * HH + c;
                #pragma unroll 4
                for (int s = 0; s < 128; s++) acc += base[(size_t)s * HH];
                d_gfpart[(b * 8 + p) * HH + c] = acc;
            }
        } else {
            int k = p - 8;
            int st = spans[(b * KSP + k) * 3 + 0];
            int en = spans[(b * KSP + k) * 3 + 1];
            float inv = 1.f / (float)(en - st + 1);
            for (int c = tid; c < HH; c += 256) {
                float a = 0.f;
                for (int s = st; s <= en; s++) a += hidden[((size_t)b * SS + s) * HH + c];
                d_nodes[(b * NN + 1 + k) * HH + c] = a * inv;
            }
        }
    }
}

// ---------- h1 partial GEMM: k-split 4-way ----------
__global__ void k_h1(const float* __restrict__ W1) {
    int n = blockIdx.x, b = blockIdx.y, z = blockIdx.z;
    int tid = threadIdx.x;
    __shared__ float sX[KCH];
    int k0 = z * KCH;
    if (n == 0) {
        for (int c = tid; c < KCH; c += 256) {
            float g = 0.f;
            #pragma unroll
            for (int p = 0; p < 8; p++) g += d_gfpart[(b * 8 + p) * HH + k0 + c];
            sX[c] = g * (1.f / (float)SS);
        }
    } else {
        for (int c = tid; c < KCH; c += 256) sX[c] = d_nodes[(b * NN + n) * HH + k0 + c];
    }
    __syncthreads();
    float acc = 0.f;
    #pragma unroll 8
    for (int d = 0; d < KCH; d++) acc += sX[d] * W1[(size_t)(k0 + d) * FF + tid];
    d_h1p[((z * BB + b) * NN + n) * FF + tid] = acc;
}

// --------- softmax over graph neighbors ---------
__device__ __forceinline__ void attn_softmax(const float* sAdjLog, const float* sAS,
                                             const float* sAD, float* sAttn, int tid) {
    if (tid < NN * NHEADS) {
        int i = tid / NHEADS, head = tid % NHEADS;
        float sc[NN];
        float mx = -1e30f;
        #pragma unroll
        for (int j = 0; j < NN; j++) {
            float al = sAdjLog[i * NN + j];
            float v;
            if (al > -1e29f) {
                float e = sAD[i * NHEADS + head] + sAS[j * NHEADS + head];
                e = (e >= 0.f) ? e : 0.2f * e;
                v = e + al;
            } else v = -1e30f;
            sc[j] = v;
            mx = fmaxf(mx, v);
        }
        float ssum = 0.f;
        #pragma unroll
        for (int j = 0; j < NN; j++) { float e = expf(sc[j] - mx); sc[j] = e; ssum += e; }
        float inv = 1.f / ssum;
        #pragma unroll
        for (int j = 0; j < NN; j++) sAttn[(i * NN + j) * NHEADS + head] = sc[j] * inv;
    }
}

// --------- adjacency (log) builder in smem ---------
__device__ __forceinline__ void build_adjlog(const int* sSp, float* sAdjLog, int tid) {
    if (tid < NN * NN) {
        int r = tid / NN, c = tid % NN;
        float v = 0.f;
        if (r == c) v += 1.f;
        if (c == 0 && r >= 1) v += 1.f;
        if (r == 0 && c >= 1) v += 1.f;
        if (r >= 1 && c >= 1 && r != c) {
            int i = r - 1, j = c - 1;
            int si = sSp[i * 2], ei = sSp[i * 2 + 1];
            int sj = sSp[j * 2], ej = sSp[j * 2 + 1];
            bool same = (sj == si) && (ej == ei);
            if ((sj <= si) && (ei <= ej) && !same) v += 2.f;
        }
        sAdjLog[tid] = (v > 0.f) ? logf(v) : -1e30f;
    }
}

// ------ gat1: h1-assemble + attn1 + g1 = LN(relu(attn@h1+b1)) -> d_g1 ------
__global__ void k_gat1(const int* __restrict__ spans,
                       const float* __restrict__ asrc1, const float* __restrict__ adst1,
                       const float* __restrict__ b1,
                       const float* __restrict__ lng, const float* __restrict__ lnb) {
    int b = blockIdx.x, tid = threadIdx.x;
    __shared__ float sH[NN * FF];
    __shared__ float sAdjLog[NN * NN];
    __shared__ float sAS[NN * NHEADS], sAD[NN * NHEADS];
    __shared__ float sAttn[NN * NN * NHEADS];
    __shared__ int sSp[KSP * 2];
    __shared__ float sWred[16], sRed[2];

    for (int i = tid; i < NN * FF; i += 256) {
        float v = 0.f;
        #pragma unroll
        for (int z = 0; z < KSPLIT; z++) v += d_h1p[(z * BB + b) * NN * FF + i];
        sH[i] = v;
    }
    if (tid < KSP * 2) sSp[tid] = spans[(b * KSP + tid / 2) * 3 + (tid & 1)];
    __syncthreads();

    if (tid < NN * NHEADS * 2) {
        int n = tid / (NHEADS * 2);
        int rem = tid % (NHEADS * 2);
        int head = rem % NHEADS;
        int isd = rem / NHEADS;
        const float* av = isd ? adst1 : asrc1;
        float acc = 0.f;
        for (int f = 0; f < HIDD; f++) acc += sH[n * FF + head * HIDD + f] * av[head * HIDD + f];
        if (isd) sAD[n * NHEADS + head] = acc;
        else     sAS[n * NHEADS + head] = acc;
    }
    if (tid >= 64 && tid - 64 < NN * NN) build_adjlog(sSp, sAdjLog, tid - 64);
    __syncthreads();
    attn_softmax(sAdjLog, sAS, sAD, sAttn, tid);
    __syncthreads();

    // g1 rows + per-row LN, written straight out
    int head = tid / HIDD;
    float gw = lng[tid], gb = lnb[tid];
    float bb = b1[tid];
    for (int i = 0; i < NN; i++) {
        float acc = bb;
        #pragma unroll
        for (int j = 0; j < NN; j++) acc += sAttn[(i * NN + j) * NHEADS + head] * sH[j * FF + tid];
        float v = fmaxf(acc, 0.f);
        float s1 = v, s2 = v * v;
        #pragma unroll
        for (int o = 16; o > 0; o >>= 1) {
            s1 += __shfl_down_sync(0xffffffffu, s1, o);
            s2 += __shfl_down_sync(0xffffffffu, s2, o);
        }
        int wid = tid >> 5, lane = tid & 31;
        if (lane == 0) { sWred[wid] = s1; sWred[8 + wid] = s2; }
        __syncthreads();
        if (tid == 0) {
            float a = 0.f, q = 0.f;
            #pragma unroll
            for (int w = 0; w < 8; w++) { a += sWred[w]; q += sWred[8 + w]; }
            float mu = a / (float)FF;
            float var = q / (float)FF - mu * mu;
            sRed[0] = mu;
            sRed[1] = rsqrtf(var + 1e-5f);
        }
        __syncthreads();
        d_g1[b * NN * FF + i * FF + tid] = (v - sRed[0]) * sRed[1] * gw + gb;
        __syncthreads();
    }
}

// ------ h2 = g1 @ W2 + a_src2/a_dst2 reductions (wide: 72 blocks) ------
__global__ void k_h2(const float* __restrict__ W2, const float* __restrict__ asrc2,
                     const float* __restrict__ adst2) {
    int n = blockIdx.x, b = blockIdx.y;
    int bn = b * NN + n;
    int tid = threadIdx.x;
    __shared__ float sX[FF];
    __shared__ float rS[8], rD[8];
    sX[tid] = d_g1[bn * FF + tid];
    __syncthreads();
    float acc = 0.f;
    #pragma unroll 8
    for (int d = 0; d < FF; d++) acc += sX[d] * W2[(size_t)d * FF + tid];
    d_h2[bn * FF + tid] = acc;
    int head = tid >> 7, dd = tid & 127;
    float vs = acc * asrc2[head * HIDD + dd];
    float vd = acc * adst2[head * HIDD + dd];
    #pragma unroll
    for (int o = 16; o > 0; o >>= 1) {
        vs += __shfl_down_sync(0xffffffffu, vs, o);
        vd += __shfl_down_sync(0xffffffffu, vd, o);
    }
    int wid = tid >> 5, lane = tid & 31;
    if (lane == 0) { rS[wid] = vs; rD[wid] = vd; }
    __syncthreads();
    if (tid < 2) {
        float s = 0.f, d2 = 0.f;
        #pragma unroll
        for (int w = 0; w < 4; w++) { s += rS[tid * 4 + w]; d2 += rD[tid * 4 + w]; }
        d_as2[bn * NHEADS + tid] = s;
        d_ad2[bn * NHEADS + tid] = d2;
    }
}

// ------ gat2: attn2 + mean -> d_enh ------
__global__ void k_gat2(const int* __restrict__ spans, const float* __restrict__ b2) {
    int b = blockIdx.x, tid = threadIdx.x;
    __shared__ float sH[NN * FF];
    __shared__ float sAdjLog[NN * NN];
    __shared__ float sAS[NN * NHEADS], sAD[NN * NHEADS];
    __shared__ float sAttn[NN * NN * NHEADS];
    __shared__ int sSp[KSP * 2];
    for (int i = tid; i < NN * FF; i += 256) sH[i] = d_h2[b * NN * FF + i];
    if (tid < KSP * 2) sSp[tid] = spans[(b * KSP + tid / 2) * 3 + (tid & 1)];
    if (tid >= 32 && tid - 32 < NN * NHEADS) {
        sAS[tid - 32] = d_as2[b * NN * NHEADS + tid - 32];
        sAD[tid - 32] = d_ad2[b * NN * NHEADS + tid - 32];
    }
    __syncthreads();
    if (tid >= 64 && tid - 64 < NN * NN) build_adjlog(sSp, sAdjLog, tid - 64);
    __syncthreads();
    attn_softmax(sAdjLog, sAS, sAD, sAttn, tid);
    __syncthreads();
    int head = tid / HIDD;
    float bb = b2[tid];
    float esum = 0.f;
    #pragma unroll
    for (int i = 0; i < NN; i++) {
        float acc = bb;
        #pragma unroll
        for (int j = 0; j < NN; j++) acc += sAttn[(i * NN + j) * NHEADS + head] * sH[j * FF + tid];
        esum += fmaxf(acc, 0.f);
    }
    d_enh[b * FF + tid] = esum * (1.f / (float)NN);
}

// ------ eW = enhanced @ dense_W[768:1024,:] (wide: 64 blocks) ------
__global__ void k_eW(const float* __restrict__ dW) {
    int b = blockIdx.y;
    int o = blockIdx.x * 128 + threadIdx.x;
    float acc = 0.f;
    #pragma unroll 8
    for (int c = 0; c < FF; c++)
        acc += d_enh[b * FF + c] * dW[(size_t)(HH + c) * OUTD + o];
    d_eW[b * OUTD + o] = acc;
}

// ------------------- bf16 MMA building blocks -------------------
__device__ __forceinline__ void g2s_cp(uint32_t dA, uint32_t dB,
        const __nv_bfloat16* __restrict__ A, const __nv_bfloat16* __restrict__ B,
        int strA, int strB, int m0, int n0, int kk, int tid) {
    #pragma unroll
    for (int i = 0; i < 2; i++) {
        int lin = tid + i * 256;
        int row = lin >> 2, ch = lin & 3;
        uint32_t off = (uint32_t)(row * 4 + (ch ^ ((row >> 1) & 3))) * 16;
        CP16(dA + off, A + (size_t)(m0 + row) * strA + kk + ch * 8);
        CP16(dB + off, B + (size_t)(n0 + row) * strB + kk + ch * 8);
    }
    CP_COMMIT();
}

__device__ __forceinline__ void tile_compute(uint32_t baseA, uint32_t baseB,
                                             int wm0, int wn0, int lane,
                                             float (&acc)[4][4][4]) {
    int rowAo = lane & 15, chAo = lane >> 4;
    int rowBo = (lane & 7) + ((lane & 16) >> 1), chBo = (lane >> 3) & 1;
    #pragma unroll
    for (int ks = 0; ks < 2; ks++) {
        uint32_t a[4][4], b[2][4];
        #pragma unroll
        for (int mi = 0; mi < 4; mi++) {
            int row = wm0 + mi * 16 + rowAo;
            int ch = ks * 2 + chAo;
            uint32_t addr = baseA + row * 64 + ((ch ^ ((row >> 1) & 3)) << 4);
            asm volatile("ldmatrix.sync.aligned.m8n8.x4.shared.b16 {%0,%1,%2,%3}, [%4];"
                : "=r"(a[mi][0]), "=r"(a[mi][1]), "=r"(a[mi][2]), "=r"(a[mi][3]) : "r"(addr));
        }
        #pragma unroll
        for (int ng = 0; ng < 2; ng++) {
            int row = wn0 + ng * 16 + rowBo;
            int ch = ks * 2 + chBo;
            uint32_t addr = baseB + row * 64 + ((ch ^ ((row >> 1) & 3)) << 4);
            asm volatile("ldmatrix.sync.aligned.m8n8.x4.shared.b16 {%0,%1,%2,%3}, [%4];"
                : "=r"(b[ng][0]), "=r"(b[ng][1]), "=r"(b[ng][2]), "=r"(b[ng][3]) : "r"(addr));
        }
        #pragma unroll
        for (int mi = 0; mi < 4; mi++)
            #pragma unroll
            for (int ni = 0; ni < 4; ni++) {
                uint32_t b0 = b[ni >> 1][(ni & 1) * 2 + 0];
                uint32_t b1 = b[ni >> 1][(ni & 1) * 2 + 1];
                asm volatile("mma.sync.aligned.m16n8k16.row.col.f32.bf16.bf16.f32 "
                    "{%0,%1,%2,%3}, {%4,%5,%6,%7}, {%8,%9}, {%0,%1,%2,%3};"
                    : "+f"(acc[mi][ni][0]), "+f"(acc[mi][ni][1]),
                      "+f"(acc[mi][ni][2]), "+f"(acc[mi][ni][3])
                    : "r"(a[mi][0]), "r"(a[mi][1]), "r"(a[mi][2]), "r"(a[mi][3]),
                      "r"(b0), "r"(b1));
            }
    }
}

// ----- GEMM1 fused: qk = hid@W^T + cover*eW + db, RoPE (fast sincos), + gaussian extras -----
__global__ void __launch_bounds__(256, 2) k_gemm1_mma(const float* __restrict__ db,
        const int* __restrict__ spans, const float* __restrict__ gc,
        const float* __restrict__ gs, const float* __restrict__ gw,
        const float* __restrict__ corr) {
    __shared__ uint4 sA[3][512], sB[3][512];
    int tid = threadIdx.x, lane = tid & 31, wid = tid >> 5;
    int m0 = blockIdx.y * 128, n0 = blockIdx.x * 128;
    int wm0 = (wid & 1) * 64, wn0 = (wid >> 1) * 32;
    float acc[4][4][4] = {};
    const int NT = HH / 32;   // 24
    g2s_cp(smem_u32(sA[0]), smem_u32(sB[0]), d_hidbf, d_wbf, HH, HH, m0, n0, 0, tid);
    g2s_cp(smem_u32(sA[1]), smem_u32(sB[1]), d_hidbf, d_wbf, HH, HH, m0, n0, 32, tid);
    for (int it = 0; it < NT; ++it) {
        CP_WAIT(1);
        __syncthreads();
        int cur = it % 3;
        tile_compute(smem_u32(sA[cur]), smem_u32(sB[cur]), wm0, wn0, lane, acc);
        if (it + 2 < NT) {
            int nxt = (it + 2) % 3;
            g2s_cp(smem_u32(sA[nxt]), smem_u32(sB[nxt]), d_hidbf, d_wbf, HH, HH,
                   m0, n0, (it + 2) * 32, tid);
        } else {
            CP_COMMIT();
        }
    }
    int g = lane >> 2, tq = lane & 3;
    int t = blockIdx.x;
    #pragma unroll
    for (int mi = 0; mi < 4; mi++) {
        #pragma unroll
        for (int half = 0; half < 2; half++) {
            int r = m0 + wm0 + mi * 16 + g + half * 8;
            int b = r >> 10, s = r & (SS - 1);
            float cov = d_cover[r];
            float sf = (float)s;
            size_t rowbase = ((size_t)(b * TT + t) * SS + s) * KEP;
            #pragma unroll
            for (int ni = 0; ni < 4; ni++) {
                int jj = wn0 + ni * 8 + tq * 2;
                int c = n0 + jj;
                float2 ew = *(const float2*)&d_eW[b * OUTD + c];
                float2 dbv = *(const float2*)&db[c];
                float x = acc[mi][ni][half * 2 + 0] + cov * ew.x + dbv.x;
                float y = acc[mi][ni][half * 2 + 1] + cov * ew.y + dbv.y;
                int i = (jj & 63) >> 1;
                float ang = sf * exp2f(-(float)i * L2C);
                float sv, cvv;
                __sincosf(ang, &sv, &cvv);
                __nv_bfloat162 v = __floats2bfloat162_rn(x * cvv - y * sv, y * cvv + x * sv);
                __nv_bfloat16* dst = ((jj < 64) ? d_qext : d_kext) + rowbase + (jj & 63);
                *(__nv_bfloat162*)dst = v;
            }
        }
    }
    // gaussian extras
    {
        int r = m0 + (tid & 127);
        int b = r >> 10, s = r & (SS - 1);
        bool isq = tid < 128;
        float sf = (float)s;
        const int* sp = spans + b * KSP * 3;
        float g0w = gw[0], g1w = gw[1];
        float g0c = gc[0], g1c = gc[1];
        float g0si = 1.f / gs[0], g1si = 1.f / gs[1];
        __nv_bfloat162* dst = (__nv_bfloat162*)(
            (isq ? d_qext : d_kext) + ((size_t)(b * TT + t) * SS + s) * KEP + 64);
        #pragma unroll
        for (int kk = 0; kk < KSP; kk++) {
            int st = sp[kk * 3], en = sp[kk * 3 + 1], et = sp[kk * 3 + 2];
            float base = isq ? (float)st : (float)en;
            float mult = isq ? corr[et * TT + t] : 1.f;
            float d0 = (sf - base - g0c) * g0si;
            float d1 = (sf - base - g1c) * g1si;
            dst[kk] = __floats2bfloat162_rn(mult * g0w * __expf(-0.5f * d0 * d0),
                                            mult * g1w * __expf(-0.5f * d1 * d1));
        }
        __nv_bfloat162 z = __floats2bfloat162_rn(0.f, 0.f);
        #pragma unroll
        for (int i = 8; i < 16; i++) dst[i] = z;
    }
}

// ------------- GEMM2: prefetch-all pipeline + mask epilogue + tril skip + streaming stores -------------
__global__ void __launch_bounds__(256, 2) k_gemm2_mma(const float* __restrict__ mask,
                                                      float* __restrict__ out) {
    __shared__ uint4 sA[3][512], sB[3][512];
    int bt = blockIdx.z;
    int b = bt >> 3;
    int tid = threadIdx.x;
    int m0 = blockIdx.y * 128, n0 = blockIdx.x * 128;

    if (m0 > n0) {
        int colq = (tid & 31) * 4;
        float4 pd = *(const float4*)&mask[b * SS + n0 + colq];
        float4 v;
        v.x = (-(1.f - pd.x) * NEGC - NEGC) * 0.125f;
        v.y = (-(1.f - pd.y) * NEGC - NEGC) * 0.125f;
        v.z = (-(1.f - pd.z) * NEGC - NEGC) * 0.125f;
        v.w = (-(1.f - pd.w) * NEGC - NEGC) * 0.125f;
        int r0 = tid >> 5;
        #pragma unroll
        for (int p = 0; p < 16; p++) {
            int m = m0 + p * 8 + r0;
            stcs4(&out[((size_t)bt * SS + m) * SS + n0 + colq], v);
        }
        return;
    }

    const __nv_bfloat16* Ab = d_qext + (size_t)bt * SS * KEP;
    const __nv_bfloat16* Bb = d_kext + (size_t)bt * SS * KEP;
    int lane = tid & 31, wid = tid >> 5;
    int wm0 = (wid & 1) * 64, wn0 = (wid >> 1) * 32;
    float acc[4][4][4] = {};
    #pragma unroll
    for (int st = 0; st < 3; st++)
        g2s_cp(smem_u32(sA[st]), smem_u32(sB[st]), Ab, Bb, KEP, KEP, m0, n0, st * 32, tid);
    CP_WAIT(0);
    __syncthreads();
    #pragma unroll
    for (int st = 0; st < 3; st++)
        tile_compute(smem_u32(sA[st]), smem_u32(sB[st]), wm0, wn0, lane, acc);

    int g = lane >> 2, tq = lane & 3;
    #pragma unroll
    for (int mi = 0; mi < 4; mi++) {
        #pragma unroll
        for (int half = 0; half < 2; half++) {
            int m = m0 + wm0 + mi * 16 + g + half * 8;
            #pragma unroll
            for (int ni = 0; ni < 4; ni++) {
                int n = n0 + wn0 + ni * 8 + tq * 2;
                float2 pd = *(const float2*)&mask[b * SS + n];
                float v0 = acc[mi][ni][half * 2 + 0] * pd.x - (1.f - pd.x) * NEGC;
                float v1 = acc[mi][ni][half * 2 + 1] * pd.y - (1.f - pd.y) * NEGC;
                if (m > n)     v0 -= NEGC;
                if (m > n + 1) v1 -= NEGC;
                stcs2(&out[((size_t)bt * SS + m) * SS + n], v0 * 0.125f, v1 * 0.125f);
            }
        }
    }
}

// ------------------- launch -------------------
extern "C" void kernel_launch(void* const* d_in, const int* in_sizes, int n_in,
                              void* d_out, int out_size) {
    const float* hidden = (const float*)d_in[0];
    const float* amask  = (const float*)d_in[1];
    const int*   spans  = (const int*)d_in[2];
    const float* W1     = (const float*)d_in[3];
    const float* asrc1  = (const float*)d_in[4];
    const float* adst1  = (const float*)d_in[5];
    const float* b1     = (const float*)d_in[6];
    const float* lng    = (const float*)d_in[7];
    const float* lnb    = (const float*)d_in[8];
    const float* W2     = (const float*)d_in[9];
    const float* asrc2  = (const float*)d_in[10];
    const float* adst2  = (const float*)d_in[11];
    const float* b2     = (const float*)d_in[12];
    const float* dW     = (const float*)d_in[13];
    const float* db     = (const float*)d_in[14];
    const float* gc     = (const float*)d_in[15];
    const float* gsg    = (const float*)d_in[16];
    const float* gwt    = (const float*)d_in[17];
    const float* corr   = (const float*)d_in[18];
    float* out = (float*)d_out;

    k_prep<<<PREP_TOTAL, 256>>>(hidden, spans, dW);
    k_h1<<<dim3(NN, BB, KSPLIT), 256>>>(W1);
    k_gat1<<<BB, 256>>>(spans, asrc1, adst1, b1, lng, lnb);
    k_h2<<<dim3(NN, BB), 256>>>(W2, asrc2, adst2);
    k_gat2<<<BB, 256>>>(spans, b2);
    k_eW<<<dim3(OUTD / 128, BB), 128>>>(dW);
    k_gemm1_mma<<<dim3(OUTD / 128, (BB * SS) / 128), 256>>>(db, spans, gc, gsg, gwt, corr);
    k_gemm2_mma<<<dim3(SS / 128, SS / 128, BB * TT), 256>>>(amask, out);
}